// round 12
// baseline (speedup 1.0000x reference)
#include <cuda_runtime.h>
#include <cuda_bf16.h>

// SymmetryConstraint — closed form per (batch, class) group (u = x - 0.5):
//   sum_{i<j}(u_i+u_j)^2 = (m-2)*sum(u^2) + (sum u)^2
//   sum_{i<j}(y_i-y_j)^2 = m*sum(y^2) - (sum y)^2
//   pairs = m*(m-1)/2
//
// R12 (= R11 retry; previous round was an infra failure):
// R9 shape (128 blocks x 256 threads, 2 batches/block, 4 pts/lane) with a
// two-level atomic publish tree:
//   level 1: 8 slot words (256B apart), slot = blockIdx & 7, 16 arrivals each
//   level 2: slot winners forward totals to one top word, 8 arrivals
// Same-address L2 drain drops from ~128 serialized ops to ~16 + 8.
// Word layout (both levels):
//   bits[ 0:30) loss in 2^-7 fixed point
//   bits[30:56) pair count
//   bits[56:64) arrival count
// All adds are commutative integers => bit-deterministic; winners reset via
// atomicExch so graph replays start clean.

#define NPTS    512
#define NBATCH  256
#define TPB     256
#define BPB     2
#define NBLOCKS (NBATCH / BPB)   // 128

#define NSLOTS     8
#define SLOT_STRIDE 32           // u64s; 256B between slot words
#define BLKS_PER_SLOT (NBLOCKS / NSLOTS)  // 16

#define LOSS_BITS 30
#define CNT_SHIFT 30
#define ARR_SHIFT 56
#define LOSS_SCALE 128.0f

__device__ unsigned long long g_slot[NSLOTS * SLOT_STRIDE];  // zero-init
__device__ unsigned long long g_top = 0ull;

__global__ __launch_bounds__(TPB)
void symconstraint_kernel(const float* __restrict__ kp,   // [B, N, 2] f32
                          const int*   __restrict__ cls,  // [B, N]    i32
                          float*       __restrict__ out)  // [1]
{
    const int t    = threadIdx.x;
    const int warp = t >> 5;            // 0..7
    const int lane = t & 31;
    const int batch_local = warp >> 2;  // 0..1
    const int wib         = warp & 3;
    const int batch       = blockIdx.x * BPB + batch_local;

    const float4* __restrict__ kp4  = reinterpret_cast<const float4*>(kp);
    const int2*   __restrict__ cls2 = reinterpret_cast<const int2*>(cls);

    const int base = batch * (NPTS / 2) + wib * 32 + lane;

    const float4 q0 = kp4 [base];
    const float4 q1 = kp4 [base + 128];
    const int2   c0 = cls2[base];
    const int2   c1 = cls2[base + 128];

    float su[3]  = {0.f, 0.f, 0.f};
    float su2[3] = {0.f, 0.f, 0.f};
    float sy[3]  = {0.f, 0.f, 0.f};
    float sy2[3] = {0.f, 0.f, 0.f};
    int   cntp   = 0;   // 3 x 10-bit packed counts

    #pragma unroll
    for (int p = 0; p < 4; p++) {
        const int   c  = (p == 0) ? c0.x : (p == 1) ? c0.y : (p == 2) ? c1.x : c1.y;
        const float xx = (p == 0) ? q0.x : (p == 1) ? q0.z : (p == 2) ? q1.x : q1.z;
        const float yy = (p == 0) ? q0.y : (p == 1) ? q0.w : (p == 2) ? q1.y : q1.w;
        const float u  = xx - 0.5f;
        const float uu = u * u;
        const float y2 = yy * yy;
        #pragma unroll
        for (int k = 0; k < 3; k++) {
            const bool h = (c == k);
            su[k]  += h ? u  : 0.f;
            su2[k] += h ? uu : 0.f;
            sy[k]  += h ? yy : 0.f;
            sy2[k] += h ? y2 : 0.f;
        }
        const unsigned uc = (unsigned)c;
        cntp += (uc <= 2u) ? (1 << (10u * (uc & 3u))) : 0;
    }

    // Warp butterfly over 13 accumulators.
    #pragma unroll
    for (int o = 16; o > 0; o >>= 1) {
        #pragma unroll
        for (int k = 0; k < 3; k++) {
            su[k]  += __shfl_xor_sync(0xffffffffu, su[k],  o);
            su2[k] += __shfl_xor_sync(0xffffffffu, su2[k], o);
            sy[k]  += __shfl_xor_sync(0xffffffffu, sy[k],  o);
            sy2[k] += __shfl_xor_sync(0xffffffffu, sy2[k], o);
        }
        cntp += __shfl_xor_sync(0xffffffffu, cntp, o);
    }

    __shared__ float s_acc[8][12];
    __shared__ int   s_cnt[8];

    if (lane == 0) {
        #pragma unroll
        for (int k = 0; k < 3; k++) {
            s_acc[warp][k]     = su[k];
            s_acc[warp][3 + k] = su2[k];
            s_acc[warp][6 + k] = sy[k];
            s_acc[warp][9 + k] = sy2[k];
        }
        s_cnt[warp] = cntp;
    }
    __syncthreads();

    // Warp 0 finishes: lanes 0/1 combine one batch's 4 warps each (branchless
    // closed form — mi in {0,1} contributes exactly 0 in fp32), fold via
    // shuffle, lane 0 publishes into the two-level atomic tree.
    if (warp == 0) {
        float loss = 0.f;
        int   pc   = 0;
        if (lane < BPB) {
            const int w0 = lane * 4;
            float a[12];
            #pragma unroll
            for (int j = 0; j < 12; j++)
                a[j] = s_acc[w0][j] + s_acc[w0 + 1][j] + s_acc[w0 + 2][j] + s_acc[w0 + 3][j];
            const int pk = s_cnt[w0] + s_cnt[w0 + 1] + s_cnt[w0 + 2] + s_cnt[w0 + 3];

            #pragma unroll
            for (int k = 0; k < 3; k++) {
                const int   mi = (pk >> (10 * k)) & 1023;
                const float m  = (float)mi;
                loss += (m - 2.f) * a[3 + k] + a[k] * a[k]
                      +  m        * a[9 + k] - a[6 + k] * a[6 + k];
                pc   += (mi * (mi - 1)) >> 1;
            }
        }
        loss += __shfl_xor_sync(0xffffffffu, loss, 1);
        pc   += __shfl_xor_sync(0xffffffffu, pc,   1);

        if (lane == 0) {
            const unsigned long long lfix =
                (unsigned long long)(loss * LOSS_SCALE + 0.5f);
            const unsigned long long mine =
                lfix
                + ((unsigned long long)pc << CNT_SHIFT)
                + (1ull << ARR_SHIFT);

            // Level 1: slot atomic (16 blocks per slot).
            unsigned long long* slotp = &g_slot[(blockIdx.x & (NSLOTS - 1)) * SLOT_STRIDE];
            const unsigned long long r1 = atomicAdd(slotp, mine);

            if ((r1 >> ARR_SHIFT) == BLKS_PER_SLOT - 1) {     // slot winner
                const unsigned long long stot = r1 + mine;
                atomicExch(slotp, 0ull);                      // replay-safe reset

                // Forward slot total with arrival field rewritten to 1.
                const unsigned long long fwd =
                    (stot & ((1ull << ARR_SHIFT) - 1)) + (1ull << ARR_SHIFT);

                // Level 2: top atomic (8 slot winners).
                const unsigned long long r2 = atomicAdd(&g_top, fwd);

                if ((r2 >> ARR_SHIFT) == NSLOTS - 1) {        // global winner
                    const unsigned long long tot = r2 + fwd;
                    const float totL = (float)(tot & ((1ull << LOSS_BITS) - 1))
                                       * (1.0f / LOSS_SCALE);
                    const float totC = (float)((tot >> CNT_SHIFT)
                                       & ((1ull << (ARR_SHIFT - CNT_SHIFT)) - 1));
                    out[0] = totL / fmaxf(totC, 1.0f);
                    atomicExch(&g_top, 0ull);                 // replay-safe reset
                }
            }
        }
    }
}

extern "C" void kernel_launch(void* const* d_in, const int* in_sizes, int n_in,
                              void* d_out, int out_size)
{
    const float* kp  = (const float*)d_in[0];
    const int*   cls = (const int*)d_in[1];
    float*       out = (float*)d_out;

    symconstraint_kernel<<<NBLOCKS, TPB>>>(kp, cls, out);
}

// round 13
// speedup vs baseline: 1.2163x; 1.2163x over previous
#include <cuda_runtime.h>
#include <cuda_bf16.h>

// SymmetryConstraint — closed form per (batch, class) group (u = x - 0.5):
//   sum_{i<j}(u_i+u_j)^2 = (m-2)*sum(u^2) + (sum u)^2
//   sum_{i<j}(y_i-y_j)^2 = m*sum(y^2) - (sum y)^2
//   pairs = m*(m-1)/2
//
// R13: 128 blocks x 512 threads (2 batches/block, 8 warps/batch, 2 pts/lane —
// one float4 + one int2 per thread). Shallowest possible per-thread front;
// single wave (128 <= 148 SMs). Tail identical to champion R9: ONE fused u64
// atomic per block,
//   bits[ 0:30) loss in 2^-7 fixed point
//   bits[30:56) pair count
//   bits[56:64) arrival count
// winner computes out[] from the atomic return. Commutative integer adds =>
// bit-deterministic; atomicExch reset => graph-replay safe.

#define NPTS    512
#define NBATCH  256
#define TPB     512
#define BPB     2
#define NBLOCKS (NBATCH / BPB)   // 128

#define LOSS_BITS 30
#define CNT_SHIFT 30
#define ARR_SHIFT 56
#define LOSS_SCALE 128.0f

__device__ unsigned long long g_all = 0ull;

__global__ __launch_bounds__(TPB)
void symconstraint_kernel(const float* __restrict__ kp,   // [B, N, 2] f32
                          const int*   __restrict__ cls,  // [B, N]    i32
                          float*       __restrict__ out)  // [1]
{
    const int t    = threadIdx.x;
    const int warp = t >> 5;            // 0..15
    const int lane = t & 31;
    const int batch_local = warp >> 3;  // 0..1
    const int wib         = warp & 7;   // warp-in-batch 0..7
    const int batch       = blockIdx.x * BPB + batch_local;

    const float4* __restrict__ kp4  = reinterpret_cast<const float4*>(kp);
    const int2*   __restrict__ cls2 = reinterpret_cast<const int2*>(cls);

    // Batch row = 256 float4 (512 points); each warp covers 32 float4 = 64 pts.
    const int base = batch * (NPTS / 2) + wib * 32 + lane;

    const float4 q  = kp4 [base];
    const int2   c2 = cls2[base];

    float su[3]  = {0.f, 0.f, 0.f};
    float su2[3] = {0.f, 0.f, 0.f};
    float sy[3]  = {0.f, 0.f, 0.f};
    float sy2[3] = {0.f, 0.f, 0.f};
    int   cntp   = 0;   // 3 x 10-bit packed counts (<=64/warp/class)

    #pragma unroll
    for (int half = 0; half < 2; half++) {
        const int   c  = half ? c2.y : c2.x;
        const float xx = half ? q.z  : q.x;
        const float yy = half ? q.w  : q.y;
        const float u  = xx - 0.5f;
        const float uu = u * u;
        const float y2 = yy * yy;
        #pragma unroll
        for (int k = 0; k < 3; k++) {
            const bool h = (c == k);
            su[k]  += h ? u  : 0.f;
            su2[k] += h ? uu : 0.f;
            sy[k]  += h ? yy : 0.f;
            sy2[k] += h ? y2 : 0.f;
        }
        const unsigned uc = (unsigned)c;
        cntp += (uc <= 2u) ? (1 << (10u * (uc & 3u))) : 0;
    }

    // Warp reduce: 12 float butterflies + 1 hardware integer redux.
    #pragma unroll
    for (int o = 16; o > 0; o >>= 1) {
        #pragma unroll
        for (int k = 0; k < 3; k++) {
            su[k]  += __shfl_xor_sync(0xffffffffu, su[k],  o);
            su2[k] += __shfl_xor_sync(0xffffffffu, su2[k], o);
            sy[k]  += __shfl_xor_sync(0xffffffffu, sy[k],  o);
            sy2[k] += __shfl_xor_sync(0xffffffffu, sy2[k], o);
        }
    }
    cntp = __reduce_add_sync(0xffffffffu, cntp);

    __shared__ float s_acc[16][12];
    __shared__ int   s_cnt[16];

    if (lane == 0) {
        #pragma unroll
        for (int k = 0; k < 3; k++) {
            s_acc[warp][k]     = su[k];
            s_acc[warp][3 + k] = su2[k];
            s_acc[warp][6 + k] = sy[k];
            s_acc[warp][9 + k] = sy2[k];
        }
        s_cnt[warp] = cntp;
    }
    __syncthreads();

    // Warp 0 finishes: lanes 0/1 each combine their batch's 8 warps
    // (branchless closed form — mi in {0,1} contributes exactly 0 in fp32),
    // fold lane 1 -> lane 0, lane 0 publishes the single fused atomic.
    if (warp == 0) {
        float loss = 0.f;
        int   pc   = 0;
        if (lane < BPB) {
            const int w0 = lane * 8;
            float a[12];
            #pragma unroll
            for (int j = 0; j < 12; j++) {
                float s = 0.f;
                #pragma unroll
                for (int w = 0; w < 8; w++) s += s_acc[w0 + w][j];
                a[j] = s;
            }
            int pk = 0;
            #pragma unroll
            for (int w = 0; w < 8; w++) pk += s_cnt[w0 + w];

            #pragma unroll
            for (int k = 0; k < 3; k++) {
                const int   mi = (pk >> (10 * k)) & 1023;
                const float m  = (float)mi;
                loss += (m - 2.f) * a[3 + k] + a[k] * a[k]
                      +  m        * a[9 + k] - a[6 + k] * a[6 + k];
                pc   += (mi * (mi - 1)) >> 1;
            }
        }
        loss += __shfl_xor_sync(0xffffffffu, loss, 1);
        pc   += __shfl_xor_sync(0xffffffffu, pc,   1);

        if (lane == 0) {
            const unsigned long long lfix =
                (unsigned long long)(loss * LOSS_SCALE + 0.5f);
            const unsigned long long mine =
                lfix
                + ((unsigned long long)pc << CNT_SHIFT)
                + (1ull << ARR_SHIFT);

            const unsigned long long ret = atomicAdd(&g_all, mine);

            if ((ret >> ARR_SHIFT) == NBLOCKS - 1) {          // we are last
                const unsigned long long tot = ret + mine;
                const float totL = (float)(tot & ((1ull << LOSS_BITS) - 1))
                                   * (1.0f / LOSS_SCALE);
                const float totC = (float)((tot >> CNT_SHIFT)
                                   & ((1ull << (ARR_SHIFT - CNT_SHIFT)) - 1));
                out[0] = totL / fmaxf(totC, 1.0f);
                atomicExch(&g_all, 0ull);                     // replay-safe reset
            }
        }
    }
}

extern "C" void kernel_launch(void* const* d_in, const int* in_sizes, int n_in,
                              void* d_out, int out_size)
{
    const float* kp  = (const float*)d_in[0];
    const int*   cls = (const int*)d_in[1];
    float*       out = (float*)d_out;

    symconstraint_kernel<<<NBLOCKS, TPB>>>(kp, cls, out);
}

// round 14
// speedup vs baseline: 1.2222x; 1.0048x over previous
#include <cuda_runtime.h>
#include <cuda_bf16.h>

// SymmetryConstraint — closed form per (batch, class) group (u = x - 0.5):
//   sum_{i<j}(u_i+u_j)^2 = (m-2)*sum(u^2) + (sum u)^2
//   sum_{i<j}(y_i-y_j)^2 = m*sum(y^2) - (sum y)^2
//   pairs = m*(m-1)/2
//
// R14: champion R9 shape (128 blocks x 256 threads, 2 batches/block, 4 pts/lane,
// ONE fused u64 atomic per block) + validated micro-wins:
//   - __reduce_add_sync for packed counts (REDUX.SYNC, -5 shuffles)
//   - branchless per-class closed form (exact for m in {0,1})
// Fused word: bits[0:30) loss (2^-7 fixed pt), [30:56) pair count, [56:64) arrivals.
// Winner computes out[] from the atomic return; atomicExch reset => replay-safe.
// Commutative integer adds => bit-deterministic under any arrival order.

#define NPTS    512
#define NBATCH  256
#define TPB     256
#define BPB     2
#define NBLOCKS (NBATCH / BPB)   // 128

#define LOSS_BITS 30
#define CNT_SHIFT 30
#define ARR_SHIFT 56
#define LOSS_SCALE 128.0f

__device__ unsigned long long g_all = 0ull;

__global__ __launch_bounds__(TPB)
void symconstraint_kernel(const float* __restrict__ kp,   // [B, N, 2] f32
                          const int*   __restrict__ cls,  // [B, N]    i32
                          float*       __restrict__ out)  // [1]
{
    const int t    = threadIdx.x;
    const int warp = t >> 5;            // 0..7
    const int lane = t & 31;
    const int batch_local = warp >> 2;  // 0..1
    const int wib         = warp & 3;
    const int batch       = blockIdx.x * BPB + batch_local;

    const float4* __restrict__ kp4  = reinterpret_cast<const float4*>(kp);
    const int2*   __restrict__ cls2 = reinterpret_cast<const int2*>(cls);

    const int base = batch * (NPTS / 2) + wib * 32 + lane;

    const float4 q0 = kp4 [base];
    const float4 q1 = kp4 [base + 128];
    const int2   c0 = cls2[base];
    const int2   c1 = cls2[base + 128];

    float su[3]  = {0.f, 0.f, 0.f};
    float su2[3] = {0.f, 0.f, 0.f};
    float sy[3]  = {0.f, 0.f, 0.f};
    float sy2[3] = {0.f, 0.f, 0.f};
    int   cntp   = 0;   // 3 x 10-bit packed counts

    #pragma unroll
    for (int p = 0; p < 4; p++) {
        const int   c  = (p == 0) ? c0.x : (p == 1) ? c0.y : (p == 2) ? c1.x : c1.y;
        const float xx = (p == 0) ? q0.x : (p == 1) ? q0.z : (p == 2) ? q1.x : q1.z;
        const float yy = (p == 0) ? q0.y : (p == 1) ? q0.w : (p == 2) ? q1.y : q1.w;
        const float u  = xx - 0.5f;
        const float uu = u * u;
        const float y2 = yy * yy;
        #pragma unroll
        for (int k = 0; k < 3; k++) {
            const bool h = (c == k);
            su[k]  += h ? u  : 0.f;
            su2[k] += h ? uu : 0.f;
            sy[k]  += h ? yy : 0.f;
            sy2[k] += h ? y2 : 0.f;
        }
        const unsigned uc = (unsigned)c;
        cntp += (uc <= 2u) ? (1 << (10u * (uc & 3u))) : 0;
    }

    // Warp reduce: 12 float butterflies (5 levels) + 1 hardware int redux.
    #pragma unroll
    for (int o = 16; o > 0; o >>= 1) {
        #pragma unroll
        for (int k = 0; k < 3; k++) {
            su[k]  += __shfl_xor_sync(0xffffffffu, su[k],  o);
            su2[k] += __shfl_xor_sync(0xffffffffu, su2[k], o);
            sy[k]  += __shfl_xor_sync(0xffffffffu, sy[k],  o);
            sy2[k] += __shfl_xor_sync(0xffffffffu, sy2[k], o);
        }
    }
    cntp = __reduce_add_sync(0xffffffffu, cntp);

    __shared__ float s_acc[8][12];
    __shared__ int   s_cnt[8];

    if (lane == 0) {
        #pragma unroll
        for (int k = 0; k < 3; k++) {
            s_acc[warp][k]     = su[k];
            s_acc[warp][3 + k] = su2[k];
            s_acc[warp][6 + k] = sy[k];
            s_acc[warp][9 + k] = sy2[k];
        }
        s_cnt[warp] = cntp;
    }
    __syncthreads();

    // Warp 0 finishes: lanes 0/1 combine one batch's 4 warps each, branchless
    // closed form, fold lane 1 -> lane 0, lane 0 publishes the fused atomic.
    if (warp == 0) {
        float loss = 0.f;
        int   pc   = 0;
        if (lane < BPB) {
            const int w0 = lane * 4;
            float a[12];
            #pragma unroll
            for (int j = 0; j < 12; j++)
                a[j] = (s_acc[w0][j] + s_acc[w0 + 1][j])
                     + (s_acc[w0 + 2][j] + s_acc[w0 + 3][j]);
            const int pk = (s_cnt[w0] + s_cnt[w0 + 1])
                         + (s_cnt[w0 + 2] + s_cnt[w0 + 3]);

            #pragma unroll
            for (int k = 0; k < 3; k++) {
                const int   mi = (pk >> (10 * k)) & 1023;
                const float m  = (float)mi;
                loss += (m - 2.f) * a[3 + k] + a[k] * a[k]
                      +  m        * a[9 + k] - a[6 + k] * a[6 + k];
                pc   += (mi * (mi - 1)) >> 1;
            }
        }
        loss += __shfl_xor_sync(0xffffffffu, loss, 1);
        pc   += __shfl_xor_sync(0xffffffffu, pc,   1);

        if (lane == 0) {
            const unsigned long long lfix =
                (unsigned long long)(loss * LOSS_SCALE + 0.5f);
            const unsigned long long mine =
                lfix
                + ((unsigned long long)pc << CNT_SHIFT)
                + (1ull << ARR_SHIFT);

            const unsigned long long ret = atomicAdd(&g_all, mine);

            if ((ret >> ARR_SHIFT) == NBLOCKS - 1) {          // we are last
                const unsigned long long tot = ret + mine;
                const float totL = (float)(tot & ((1ull << LOSS_BITS) - 1))
                                   * (1.0f / LOSS_SCALE);
                const float totC = (float)((tot >> CNT_SHIFT)
                                   & ((1ull << (ARR_SHIFT - CNT_SHIFT)) - 1));
                out[0] = totL / fmaxf(totC, 1.0f);
                atomicExch(&g_all, 0ull);                     // replay-safe reset
            }
        }
    }
}

extern "C" void kernel_launch(void* const* d_in, const int* in_sizes, int n_in,
                              void* d_out, int out_size)
{
    const float* kp  = (const float*)d_in[0];
    const int*   cls = (const int*)d_in[1];
    float*       out = (float*)d_out;

    symconstraint_kernel<<<NBLOCKS, TPB>>>(kp, cls, out);
}